// round 4
// baseline (speedup 1.0000x reference)
#include <cuda_runtime.h>
#include <stdint.h>

// Problem: B x N fp32 scores. Outputs (concatenated into float d_out):
//   [0, B*N)      portfolio_weights (sparse +softmax(top20), -softmax(bot20))
//   [B*N, 2*B*N)  sorted_indices of argsort(-scores) as float
#define N_COLS 8192
#define NB     512    // equal-probability buckets per row (avg 16 elems)
#define NT     1024   // threads per CTA (one CTA per row)
#define NWARP  32

// Monotone value->bucket table, indexed by top 16 bits of descending sort key.
__device__ unsigned short g_bucket_tab[65536];

// ---------------------------------------------------------------------------
// Build bucket table from normal CDF (equal-probability buckets for N(0,1)).
// dkey = ~sortable(x); ascending dkey == descending x. Table must be monotone
// non-decreasing in the 16-bit prefix; fix_table enforces that exactly.
// ---------------------------------------------------------------------------
__global__ void pg_build_table_kernel() {
    int j = blockIdx.x * blockDim.x + threadIdx.x;   // 0..65535
    unsigned int dkey = ((unsigned int)j) << 16;
    unsigned int ukey = ~dkey;
    float x;
    if (ukey & 0x80000000u) x = __uint_as_float(ukey ^ 0x80000000u);
    else                    x = __uint_as_float(~ukey);
    int b;
    if (!(x == x)) {
        b = (ukey & 0x80000000u) ? 0 : (NB - 1);
    } else {
        float xc = fminf(fmaxf(x, -30.0f), 30.0f);
        float q = normcdff(-xc);                     // monotone decreasing in x
        int bb = (int)floorf(q * (float)NB);
        b = bb < 0 ? 0 : (bb > NB - 1 ? NB - 1 : bb);
    }
    g_bucket_tab[j] = (unsigned short)b;
}

// Enforce monotone non-decreasing table via block-wide running max.
__global__ void pg_fix_table_kernel() {
    __shared__ int tmax[NT];
    int t = threadIdx.x;
    int base = t * 64;
    int cm = 0;
    for (int i = 0; i < 64; i++) cm = max(cm, (int)g_bucket_tab[base + i]);
    tmax[t] = cm;
    __syncthreads();
    for (int d = 1; d < NT; d <<= 1) {
        int v = (t >= d) ? tmax[t - d] : 0;
        __syncthreads();
        if (t >= d) tmax[t] = max(tmax[t], v);
        __syncthreads();
    }
    int run = (t == 0) ? 0 : tmax[t - 1];   // exclusive prefix max
    for (int i = 0; i < 64; i++) {
        int v = (int)g_bucket_tab[base + i];
        run = max(run, v);
        g_bucket_tab[base + i] = (unsigned short)run;
    }
}

// ---------------------------------------------------------------------------
// Main kernel: one CTA per row. ZERO atomics.
// Phase 1: load row; per-warp match-based ranking into per-warp histograms.
// Phase 2: cross-warp per-bucket offsets + block scan of bucket totals.
// Phase 3: scatter packed (dkey|idx) u64 to exact position (no atomics).
// Phase 4: per-bucket insertion sort (avg 16 elems/bucket).
// Phase 5: write sorted indices; zero weights row; softmax top/bot 20.
//
// SMEM layout (bytes):
//   [0,      65536)  data    u64[8192]
//   [65536,  98304)  whist   u16[32*512]  per-warp bucket counts / offsets
//   [98304, 100352)  base    u32[512]     global exclusive bucket offsets
//   [100352,102400)  tot     u32[512]     bucket counts
//   [102400,102528)  wsum    u32[32]
//   [102528,102688)  sc_val  f32[40]
//   [102688,102848)  sc_idx  i32[40]
// ---------------------------------------------------------------------------
#define SMEM_BYTES 102848

__global__ void __launch_bounds__(NT)
pg_sort_kernel(const float* __restrict__ in, float* __restrict__ out,
               int B, int write_indices) {
    extern __shared__ unsigned char smem_raw[];
    unsigned long long* data = (unsigned long long*)smem_raw;
    unsigned short* whist = (unsigned short*)(smem_raw + 65536);
    unsigned int* base = (unsigned int*)(smem_raw + 98304);
    unsigned int* tot  = (unsigned int*)(smem_raw + 100352);
    unsigned int* wsum = (unsigned int*)(smem_raw + 102400);
    float* sc_val = (float*)(smem_raw + 102528);
    int*   sc_idx = (int*)  (smem_raw + 102688);

    int row = blockIdx.x;
    int tid = threadIdx.x;
    int lane = tid & 31;
    int wid = tid >> 5;
    const float* rowp = in + (size_t)row * N_COLS;
    const float4* rowp4 = (const float4*)rowp;

    // zero per-warp histograms (16384 u16 = 8192 u32)
    unsigned int* whist32 = (unsigned int*)whist;
    for (int j = tid; j < 8192; j += NT) whist32[j] = 0;
    __syncthreads();

    // ---- Phase 1: load 8 values/thread, keys, match-based per-warp ranking
    float4 v0 = rowp4[tid];
    float4 v1 = rowp4[tid + NT];
    unsigned int dk[8];
    {
        float vv[8] = {v0.x, v0.y, v0.z, v0.w, v1.x, v1.y, v1.z, v1.w};
#pragma unroll
        for (int k = 0; k < 8; k++) {
            unsigned int u = __float_as_uint(vv[k]);
            unsigned int ukey = (u & 0x80000000u) ? ~u : (u | 0x80000000u);
            dk[k] = ~ukey;   // ascending dk == descending value
        }
    }
    unsigned short* wh = whist + wid * NB;   // this warp's private histogram
    unsigned int bk[8];                      // packed (bucket<<16)|warp_rank
    unsigned int ltmask = (1u << lane) - 1u;
#pragma unroll
    for (int k = 0; k < 8; k++) {
        unsigned int b = (unsigned int)g_bucket_tab[dk[k] >> 16];
        unsigned int mask = __match_any_sync(0xFFFFFFFFu, b);
        int leader = __ffs(mask) - 1;
        unsigned int before = 0;
        if (lane == leader) {
            before = (unsigned int)wh[b];
            wh[b] = (unsigned short)(before + (unsigned int)__popc(mask));
        }
        before = __shfl_sync(0xFFFFFFFFu, before, leader);
        unsigned int r = before + (unsigned int)__popc(mask & ltmask);
        bk[k] = (b << 16) | r;
        __syncwarp();
    }
    __syncthreads();

    // ---- Phase 2: per-bucket cross-warp exclusive offsets + bucket totals
    unsigned int cnt = 0, inc = 0;
    if (tid < NB) {
        unsigned int run = 0;
        for (int w = 0; w < NWARP; w++) {
            unsigned int c = (unsigned int)whist[w * NB + tid];
            whist[w * NB + tid] = (unsigned short)run;  // per-warp exclusive
            run += c;
        }
        tot[tid] = run;
        cnt = run;
        // warp-inclusive scan over bucket counts (warps 0..15 fully active)
        inc = cnt;
#pragma unroll
        for (int d = 1; d < 32; d <<= 1) {
            unsigned int v = __shfl_up_sync(0xFFFFFFFFu, inc, d);
            if (lane >= d) inc += v;
        }
        if (lane == 31) wsum[wid] = inc;
    }
    __syncthreads();
    if (tid < 16) {
        unsigned int w = wsum[tid];
        unsigned int wi = w;
#pragma unroll
        for (int d = 1; d < 16; d <<= 1) {
            unsigned int v = __shfl_up_sync(0x0000FFFFu, wi, d);
            if (tid >= d) wi += v;
        }
        wsum[tid] = wi - w;   // exclusive warp offsets
    }
    __syncthreads();
    if (tid < NB) base[tid] = inc - cnt + wsum[wid];
    __syncthreads();

    // ---- Phase 3: scatter to exact positions (no atomics)
#pragma unroll
    for (int k = 0; k < 8; k++) {
        unsigned int b = bk[k] >> 16;
        unsigned int r = bk[k] & 0xFFFFu;
        unsigned int pos = base[b] + (unsigned int)wh[b] + r;
        int idx = (k < 4) ? (4 * tid + k) : (4 * (tid + NT) + (k - 4));
        data[pos] = ((unsigned long long)dk[k] << 32) | (unsigned int)idx;
    }
    __syncthreads();

    // ---- Phase 4: per-bucket insertion sort (ascending u64)
    if (tid < NB) {
        int start = (int)base[tid];
        int end = start + (int)tot[tid];
        for (int i = start + 1; i < end; i++) {
            unsigned long long v = data[i];
            int k = i - 1;
            while (k >= start && data[k] > v) { data[k + 1] = data[k]; k--; }
            data[k + 1] = v;
        }
    }
    __syncthreads();

    // ---- Phase 5: outputs
    if (write_indices) {
        float4* oidx4 = (float4*)(out + (size_t)B * N_COLS + (size_t)row * N_COLS);
#pragma unroll
        for (int g = 0; g < 2; g++) {
            int b4 = 4 * (tid + g * NT);
            float4 f;
            f.x = (float)(unsigned int)(data[b4 + 0] & 0xFFFFFFFFull);
            f.y = (float)(unsigned int)(data[b4 + 1] & 0xFFFFFFFFull);
            f.z = (float)(unsigned int)(data[b4 + 2] & 0xFFFFFFFFull);
            f.w = (float)(unsigned int)(data[b4 + 3] & 0xFFFFFFFFull);
            oidx4[tid + g * NT] = f;
        }
    }

    float* ow = out + (size_t)row * N_COLS;
    float4* ow4 = (float4*)ow;
    float4 z = make_float4(0.f, 0.f, 0.f, 0.f);
    ow4[tid] = z;
    ow4[tid + NT] = z;

    if (tid < 20) {
        int idx = (int)(data[tid] & 0xFFFFFFFFull);
        sc_idx[tid] = idx;
        sc_val[tid] = rowp[idx];
    } else if (tid < 40) {
        int k = tid - 20;
        int idx = (int)(data[N_COLS - 20 + k] & 0xFFFFFFFFull);
        sc_idx[tid] = idx;
        sc_val[tid] = -rowp[idx];   // bot_scores = -score
    }
    __syncthreads();  // orders the zero-fill stores before the scatter below

    if (tid < 40) {
        int g0 = (tid < 20) ? 0 : 20;
        float m = -1e30f;
#pragma unroll
        for (int j = 0; j < 20; j++) m = fmaxf(m, sc_val[g0 + j]);
        float s = 0.f;
#pragma unroll
        for (int j = 0; j < 20; j++) s += expf(sc_val[g0 + j] - m);
        float w = expf(sc_val[tid] - m) / s;
        ow[sc_idx[tid]] = (tid < 20) ? w : -w;
    }
}

extern "C" void kernel_launch(void* const* d_in, const int* in_sizes, int n_in,
                              void* d_out, int out_size) {
    const float* in = (const float*)d_in[0];
    float* out = (float*)d_out;
    int total = in_sizes[0];
    int B = total / N_COLS;
    int write_indices = (out_size >= 2 * total) ? 1 : 0;

    cudaFuncSetAttribute(pg_sort_kernel,
                         cudaFuncAttributeMaxDynamicSharedMemorySize, SMEM_BYTES);

    pg_build_table_kernel<<<64, 1024>>>();
    pg_fix_table_kernel<<<1, NT>>>();
    pg_sort_kernel<<<B, NT, SMEM_BYTES>>>(in, out, B, write_indices);
}

// round 5
// speedup vs baseline: 1.2401x; 1.2401x over previous
#include <cuda_runtime.h>
#include <stdint.h>

// Problem: B x N fp32 scores. Outputs (concatenated into float d_out):
//   [0, B*N)      portfolio_weights (sparse +softmax(top20), -softmax(bot20))
//   [B*N, 2*B*N)  sorted_indices of argsort(-scores) as float
#define N_COLS 8192
#define NB     1024   // equal-probability buckets per row (avg 8 elems)
#define NT     1024   // threads per CTA (one CTA per row)
#define NWARP  32

// Monotone value->bucket table, indexed by top 16 bits of descending sort key.
__device__ unsigned short g_bucket_tab[65536];

// ---------------------------------------------------------------------------
// Build bucket table from normal CDF (equal-probability buckets for N(0,1)).
// dkey = ~sortable(x); ascending dkey == descending x. Table must be monotone
// non-decreasing in the 16-bit prefix; fix_table enforces that exactly.
// ---------------------------------------------------------------------------
__global__ void pg_build_table_kernel() {
    int j = blockIdx.x * blockDim.x + threadIdx.x;   // 0..65535
    unsigned int dkey = ((unsigned int)j) << 16;
    unsigned int ukey = ~dkey;
    float x;
    if (ukey & 0x80000000u) x = __uint_as_float(ukey ^ 0x80000000u);
    else                    x = __uint_as_float(~ukey);
    int b;
    if (!(x == x)) {
        b = (ukey & 0x80000000u) ? 0 : (NB - 1);
    } else {
        float xc = fminf(fmaxf(x, -30.0f), 30.0f);
        float q = normcdff(-xc);                     // monotone decreasing in x
        int bb = (int)floorf(q * (float)NB);
        b = bb < 0 ? 0 : (bb > NB - 1 ? NB - 1 : bb);
    }
    g_bucket_tab[j] = (unsigned short)b;
}

// Enforce monotone non-decreasing table via block-wide running max.
__global__ void pg_fix_table_kernel() {
    __shared__ int tmax[NT];
    int t = threadIdx.x;
    int base = t * 64;
    int cm = 0;
    for (int i = 0; i < 64; i++) cm = max(cm, (int)g_bucket_tab[base + i]);
    tmax[t] = cm;
    __syncthreads();
    for (int d = 1; d < NT; d <<= 1) {
        int v = (t >= d) ? tmax[t - d] : 0;
        __syncthreads();
        if (t >= d) tmax[t] = max(tmax[t], v);
        __syncthreads();
    }
    int run = (t == 0) ? 0 : tmax[t - 1];   // exclusive prefix max
    for (int i = 0; i < 64; i++) {
        int v = (int)g_bucket_tab[base + i];
        run = max(run, v);
        g_bucket_tab[base + i] = (unsigned short)run;
    }
}

// ---------------------------------------------------------------------------
// Main kernel: one CTA per row. ZERO atomics.
// Phase 1: load row; per-warp match-based ranking into per-warp u8 histograms.
// Phase 2: transposed cross-warp offsets (each thread owns one bucket) +
//          block scan of bucket totals.
// Phase 3: scatter packed (dkey|idx) u64 to exact position.
// Phase 4: per-bucket insertion sort on the u64 keys (avg 8/bucket; ties
//          resolved exactly here since idx is in the low 32 bits).
// Phase 5: write sorted indices; zero weights row; softmax top/bot 20.
//
// SMEM layout (bytes):
//   [0,      65536)  data    u64[8192]
//   [65536,  98304)  whist   u8[32][1024]  per-warp bucket counts / offsets
//   [98304, 102400)  base    u32[1024]     global exclusive bucket offsets
//   [102400,106496)  tot     u32[1024]     bucket counts
//   [106496,106624)  wsum    u32[32]
//   [106624,106784)  sc_val  f32[40]
//   [106784,106944)  sc_idx  i32[40]
// ---------------------------------------------------------------------------
#define SMEM_BYTES 106944

__global__ void __launch_bounds__(NT)
pg_sort_kernel(const float* __restrict__ in, float* __restrict__ out,
               int B, int write_indices, int row0) {
    extern __shared__ unsigned char smem_raw[];
    unsigned long long* data = (unsigned long long*)smem_raw;
    unsigned char* whist = (unsigned char*)(smem_raw + 65536);
    unsigned int* base = (unsigned int*)(smem_raw + 98304);
    unsigned int* tot  = (unsigned int*)(smem_raw + 102400);
    unsigned int* wsum = (unsigned int*)(smem_raw + 106496);
    float* sc_val = (float*)(smem_raw + 106624);
    int*   sc_idx = (int*)  (smem_raw + 106784);

    int row = row0 + blockIdx.x;
    int tid = threadIdx.x;
    int lane = tid & 31;
    int wid = tid >> 5;
    const float* rowp = in + (size_t)row * N_COLS;
    const float4* rowp4 = (const float4*)rowp;

    // zero per-warp histograms (32768 B = 8192 u32)
    unsigned int* whist32 = (unsigned int*)whist;
#pragma unroll
    for (int j = 0; j < 8; j++) whist32[tid + j * NT] = 0;
    __syncthreads();

    // ---- Phase 1: load 8 values/thread, keys, match-based per-warp ranking
    float4 v0 = rowp4[tid];
    float4 v1 = rowp4[tid + NT];
    unsigned int dk[8];
    {
        float vv[8] = {v0.x, v0.y, v0.z, v0.w, v1.x, v1.y, v1.z, v1.w};
#pragma unroll
        for (int k = 0; k < 8; k++) {
            unsigned int u = __float_as_uint(vv[k]);
            unsigned int ukey = (u & 0x80000000u) ? ~u : (u | 0x80000000u);
            dk[k] = ~ukey;   // ascending dk == descending value
        }
    }
    unsigned char* wh = whist + wid * NB;    // this warp's private histogram
    unsigned int bk[8];                      // packed (bucket<<8)|warp_rank
    unsigned int ltmask = (1u << lane) - 1u;
#pragma unroll
    for (int k = 0; k < 8; k++) {
        unsigned int b = (unsigned int)g_bucket_tab[dk[k] >> 16];
        unsigned int mask = __match_any_sync(0xFFFFFFFFu, b);
        int leader = __ffs(mask) - 1;
        unsigned int before = 0;
        if (lane == leader) {
            before = (unsigned int)wh[b];
            wh[b] = (unsigned char)(before + (unsigned int)__popc(mask));
        }
        before = __shfl_sync(0xFFFFFFFFu, before, leader);
        unsigned int r = before + (unsigned int)__popc(mask & ltmask);
        bk[k] = (b << 8) | r;
        __syncwarp();
    }
    __syncthreads();

    // ---- Phase 2: cross-warp exclusive offsets (1 bucket per thread)
    unsigned int cnt, inc;
    {
        unsigned int c[NWARP];
#pragma unroll
        for (int w = 0; w < NWARP; w++) c[w] = (unsigned int)whist[w * NB + tid];
        unsigned int run = 0;
#pragma unroll
        for (int w = 0; w < NWARP; w++) {
            whist[w * NB + tid] = (unsigned char)run;  // per-warp exclusive
            run += c[w];
        }
        tot[tid] = run;
        cnt = run;
        inc = cnt;
#pragma unroll
        for (int d = 1; d < 32; d <<= 1) {
            unsigned int v = __shfl_up_sync(0xFFFFFFFFu, inc, d);
            if (lane >= d) inc += v;
        }
        if (lane == 31) wsum[wid] = inc;
    }
    __syncthreads();
    if (tid < 32) {
        unsigned int w = wsum[tid];
        unsigned int wi = w;
#pragma unroll
        for (int d = 1; d < 32; d <<= 1) {
            unsigned int v = __shfl_up_sync(0xFFFFFFFFu, wi, d);
            if (tid >= d) wi += v;
        }
        wsum[tid] = wi - w;   // exclusive warp offsets
    }
    __syncthreads();
    base[tid] = inc - cnt + wsum[wid];
    __syncthreads();

    // ---- Phase 3: scatter to exact positions (no atomics)
#pragma unroll
    for (int k = 0; k < 8; k++) {
        unsigned int b = bk[k] >> 8;
        unsigned int r = bk[k] & 0xFFu;
        unsigned int pos = base[b] + (unsigned int)whist[wid * NB + b] + r;
        int idx = (k < 4) ? (4 * tid + k) : (4 * (tid + NT) + (k - 4));
        data[pos] = ((unsigned long long)dk[k] << 32) | (unsigned int)idx;
    }
    __syncthreads();

    // ---- Phase 4: per-bucket insertion sort (ascending u64; exact tie order)
    {
        int start = (int)base[tid];
        int end = start + (int)tot[tid];
        for (int i = start + 1; i < end; i++) {
            unsigned long long v = data[i];
            int k = i - 1;
            while (k >= start && data[k] > v) { data[k + 1] = data[k]; k--; }
            data[k + 1] = v;
        }
    }
    __syncthreads();

    // ---- Phase 5: outputs
    if (write_indices) {
        float4* oidx4 = (float4*)(out + (size_t)B * N_COLS + (size_t)row * N_COLS);
#pragma unroll
        for (int g = 0; g < 2; g++) {
            int b4 = 4 * (tid + g * NT);
            float4 f;
            f.x = (float)(unsigned int)(data[b4 + 0] & 0xFFFFFFFFull);
            f.y = (float)(unsigned int)(data[b4 + 1] & 0xFFFFFFFFull);
            f.z = (float)(unsigned int)(data[b4 + 2] & 0xFFFFFFFFull);
            f.w = (float)(unsigned int)(data[b4 + 3] & 0xFFFFFFFFull);
            oidx4[tid + g * NT] = f;
        }
    }

    float* ow = out + (size_t)row * N_COLS;
    float4* ow4 = (float4*)ow;
    float4 z = make_float4(0.f, 0.f, 0.f, 0.f);
    ow4[tid] = z;
    ow4[tid + NT] = z;

    if (tid < 20) {
        int idx = (int)(data[tid] & 0xFFFFFFFFull);
        sc_idx[tid] = idx;
        sc_val[tid] = rowp[idx];
    } else if (tid < 40) {
        int k = tid - 20;
        int idx = (int)(data[N_COLS - 20 + k] & 0xFFFFFFFFull);
        sc_idx[tid] = idx;
        sc_val[tid] = -rowp[idx];   // bot_scores = -score
    }
    __syncthreads();  // orders the zero-fill stores before the scatter below

    if (tid < 40) {
        int g0 = (tid < 20) ? 0 : 20;
        float m = -1e30f;
#pragma unroll
        for (int j = 0; j < 20; j++) m = fmaxf(m, sc_val[g0 + j]);
        float s = 0.f;
#pragma unroll
        for (int j = 0; j < 20; j++) s += expf(sc_val[g0 + j] - m);
        float w = expf(sc_val[tid] - m) / s;
        ow[sc_idx[tid]] = (tid < 20) ? w : -w;
    }
}

extern "C" void kernel_launch(void* const* d_in, const int* in_sizes, int n_in,
                              void* d_out, int out_size) {
    const float* in = (const float*)d_in[0];
    float* out = (float*)d_out;
    int total = in_sizes[0];
    int B = total / N_COLS;
    int write_indices = (out_size >= 2 * total) ? 1 : 0;

    cudaFuncSetAttribute(pg_sort_kernel,
                         cudaFuncAttributeMaxDynamicSharedMemorySize, SMEM_BYTES);

    pg_build_table_kernel<<<64, 1024>>>();
    pg_fix_table_kernel<<<1, NT>>>();

    // Split the row range into 4 launches (profiling visibility; negligible cost).
    int chunk = (B + 3) / 4;
    for (int r0 = 0; r0 < B; r0 += chunk) {
        int nrows = (B - r0 < chunk) ? (B - r0) : chunk;
        pg_sort_kernel<<<nrows, NT, SMEM_BYTES>>>(in, out, B, write_indices, r0);
    }
}

// round 6
// speedup vs baseline: 1.4052x; 1.1331x over previous
#include <cuda_runtime.h>
#include <stdint.h>

// Problem: B x N fp32 scores. Outputs (concatenated into float d_out):
//   [0, B*N)      portfolio_weights (sparse +softmax(top20), -softmax(bot20))
//   [B*N, 2*B*N)  sorted_indices of argsort(-scores) as float
#define N_COLS 8192
#define NB     1024   // equal-probability buckets per row (avg 8 elems)
#define NT     1024   // threads per CTA (one CTA per row)
#define NWARP  32

// Monotone value->bucket table, indexed by top 16 bits of descending sort key.
__device__ unsigned short g_bucket_tab[65536];

__global__ void pg_build_table_kernel() {
    int j = blockIdx.x * blockDim.x + threadIdx.x;   // 0..65535
    unsigned int dkey = ((unsigned int)j) << 16;
    unsigned int ukey = ~dkey;
    float x;
    if (ukey & 0x80000000u) x = __uint_as_float(ukey ^ 0x80000000u);
    else                    x = __uint_as_float(~ukey);
    int b;
    if (!(x == x)) {
        b = (ukey & 0x80000000u) ? 0 : (NB - 1);
    } else {
        float xc = fminf(fmaxf(x, -30.0f), 30.0f);
        float q = normcdff(-xc);                     // monotone decreasing in x
        int bb = (int)floorf(q * (float)NB);
        b = bb < 0 ? 0 : (bb > NB - 1 ? NB - 1 : bb);
    }
    g_bucket_tab[j] = (unsigned short)b;
}

// Enforce monotone non-decreasing table via block-wide running max.
__global__ void pg_fix_table_kernel() {
    __shared__ int tmax[NT];
    int t = threadIdx.x;
    int base = t * 64;
    int cm = 0;
    for (int i = 0; i < 64; i++) cm = max(cm, (int)g_bucket_tab[base + i]);
    tmax[t] = cm;
    __syncthreads();
    for (int d = 1; d < NT; d <<= 1) {
        int v = (t >= d) ? tmax[t - d] : 0;
        __syncthreads();
        if (t >= d) tmax[t] = max(tmax[t], v);
        __syncthreads();
    }
    int run = (t == 0) ? 0 : tmax[t - 1];   // exclusive prefix max
    for (int i = 0; i < 64; i++) {
        int v = (int)g_bucket_tab[base + i];
        run = max(run, v);
        g_bucket_tab[base + i] = (unsigned short)run;
    }
}

// ---------------------------------------------------------------------------
// SMEM layout (bytes):
//   [0,      65536)  data    u64[8192]
//   [65536,  98304)  whist   u8[32][1024]  per-warp counts -> exclusive offs
//   [98304, 102400)  base    u32[1024]     global exclusive bucket offsets
//   [102400,102528)  wsum    u32[32]
//   [102528,102688)  sc_val  f32[40]
//   [102688,102848)  sc_idx  i32[40]
// Total 102848 B -> two CTAs per SM (205696 <= 228KB) once regs <= 32.
// ---------------------------------------------------------------------------
#define SMEM_BYTES 102848

__device__ __forceinline__ unsigned int desc_key(float x) {
    unsigned int u = __float_as_uint(x);
    unsigned int ukey = (u & 0x80000000u) ? ~u : (u | 0x80000000u);
    return ~ukey;   // ascending key == descending value
}

__global__ void __launch_bounds__(NT, 2)
pg_sort_kernel(const float* __restrict__ in, float* __restrict__ out,
               int B, int write_indices, int row0) {
    extern __shared__ unsigned char smem_raw[];
    unsigned long long* data = (unsigned long long*)smem_raw;
    unsigned char* whist = (unsigned char*)(smem_raw + 65536);
    unsigned int* base = (unsigned int*)(smem_raw + 98304);
    unsigned int* wsum = (unsigned int*)(smem_raw + 102400);
    float* sc_val = (float*)(smem_raw + 102528);
    int*   sc_idx = (int*)  (smem_raw + 102688);

    int row = row0 + blockIdx.x;
    int tid = threadIdx.x;
    int lane = tid & 31;
    int wid = tid >> 5;
    const float4* rowp4 = (const float4*)(in + (size_t)row * N_COLS);

    // zero per-warp histograms (32768 B) with 128-bit stores
    {
        uint4* whist128 = (uint4*)whist;
        uint4 z4 = make_uint4(0, 0, 0, 0);
        whist128[tid] = z4;
        whist128[tid + NT] = z4;
    }
    __syncthreads();

    // ---- Phase 1: match-based per-warp ranking (keys recomputed later)
    unsigned int bk[8];                      // packed (bucket<<8)|warp_rank
    {
        float4 v0 = rowp4[tid];
        float4 v1 = rowp4[tid + NT];
        float vv[8] = {v0.x, v0.y, v0.z, v0.w, v1.x, v1.y, v1.z, v1.w};
        unsigned char* wh = whist + wid * NB;
        unsigned int ltmask = (1u << lane) - 1u;
#pragma unroll
        for (int k = 0; k < 8; k++) {
            unsigned int b = (unsigned int)g_bucket_tab[desc_key(vv[k]) >> 16];
            unsigned int mask = __match_any_sync(0xFFFFFFFFu, b);
            int leader = __ffs(mask) - 1;
            unsigned int before = 0;
            if (lane == leader) {
                before = (unsigned int)wh[b];
                wh[b] = (unsigned char)(before + (unsigned int)__popc(mask));
            }
            before = __shfl_sync(0xFFFFFFFFu, before, leader);
            unsigned int r = before + (unsigned int)__popc(mask & ltmask);
            bk[k] = (b << 8) | r;
            __syncwarp();
        }
    }
    __syncthreads();

    // ---- Phase 2: cross-warp exclusive offsets (1 bucket per thread)
    {
        unsigned int c[NWARP];
#pragma unroll
        for (int w = 0; w < NWARP; w++) c[w] = (unsigned int)whist[w * NB + tid];
        unsigned int run = 0;
#pragma unroll
        for (int w = 0; w < NWARP; w++) {
            whist[w * NB + tid] = (unsigned char)run;  // per-warp exclusive
            run += c[w];
        }
        unsigned int cnt = run;
        unsigned int inc = cnt;
#pragma unroll
        for (int d = 1; d < 32; d <<= 1) {
            unsigned int v = __shfl_up_sync(0xFFFFFFFFu, inc, d);
            if (lane >= d) inc += v;
        }
        if (lane == 31) wsum[wid] = inc;
        __syncthreads();
        if (tid < 32) {
            unsigned int w = wsum[tid];
            unsigned int wi = w;
#pragma unroll
            for (int d = 1; d < 32; d <<= 1) {
                unsigned int v = __shfl_up_sync(0xFFFFFFFFu, wi, d);
                if (tid >= d) wi += v;
            }
            wsum[tid] = wi - w;   // exclusive warp offsets
        }
        __syncthreads();
        base[tid] = inc - cnt + wsum[wid];
    }
    __syncthreads();

    // ---- Phase 3: scatter to exact positions (keys recomputed from L2)
    {
        float4 v0 = rowp4[tid];
        float4 v1 = rowp4[tid + NT];
        float vv[8] = {v0.x, v0.y, v0.z, v0.w, v1.x, v1.y, v1.z, v1.w};
#pragma unroll
        for (int k = 0; k < 8; k++) {
            unsigned int dk = desc_key(vv[k]);
            unsigned int b = bk[k] >> 8;
            unsigned int r = bk[k] & 0xFFu;
            unsigned int pos = base[b] + (unsigned int)whist[wid * NB + b] + r;
            int idx = (k < 4) ? (4 * tid + k) : (4 * (tid + NT) + (k - 4));
            data[pos] = ((unsigned long long)dk << 32) | (unsigned int)idx;
        }
    }
    __syncthreads();

    // ---- Phase 4: per-bucket insertion sort (ascending u64; exact ties)
    {
        int start = (int)base[tid];
        int end = (tid < NB - 1) ? (int)base[tid + 1] : N_COLS;
        for (int i = start + 1; i < end; i++) {
            unsigned long long v = data[i];
            int k = i - 1;
            while (k >= start && data[k] > v) { data[k + 1] = data[k]; k--; }
            data[k + 1] = v;
        }
    }
    __syncthreads();

    // ---- Phase 5: outputs
    if (write_indices) {
        float4* oidx4 = (float4*)(out + (size_t)B * N_COLS + (size_t)row * N_COLS);
#pragma unroll
        for (int g = 0; g < 2; g++) {
            int b4 = 4 * (tid + g * NT);
            float4 f;
            f.x = (float)(unsigned int)(data[b4 + 0] & 0xFFFFFFFFull);
            f.y = (float)(unsigned int)(data[b4 + 1] & 0xFFFFFFFFull);
            f.z = (float)(unsigned int)(data[b4 + 2] & 0xFFFFFFFFull);
            f.w = (float)(unsigned int)(data[b4 + 3] & 0xFFFFFFFFull);
            oidx4[tid + g * NT] = f;
        }
    }

    float* ow = out + (size_t)row * N_COLS;
    float4* ow4 = (float4*)ow;
    float4 z = make_float4(0.f, 0.f, 0.f, 0.f);
    ow4[tid] = z;
    ow4[tid + NT] = z;

    // reconstruct scores exactly from the sort keys (no global gather)
    if (tid < 40) {
        int src = (tid < 20) ? tid : (N_COLS - 20 + (tid - 20));
        unsigned long long e = data[src];
        unsigned int dk = (unsigned int)(e >> 32);
        unsigned int ukey = ~dk;
        float x = (ukey & 0x80000000u) ? __uint_as_float(ukey ^ 0x80000000u)
                                       : __uint_as_float(~ukey);
        sc_idx[tid] = (int)(e & 0xFFFFFFFFull);
        sc_val[tid] = (tid < 20) ? x : -x;
    }
    __syncthreads();  // orders the zero-fill stores before the scatter below

    if (tid < 40) {
        int g0 = (tid < 20) ? 0 : 20;
        float m = -1e30f;
#pragma unroll
        for (int j = 0; j < 20; j++) m = fmaxf(m, sc_val[g0 + j]);
        float s = 0.f;
#pragma unroll
        for (int j = 0; j < 20; j++) s += expf(sc_val[g0 + j] - m);
        float w = expf(sc_val[tid] - m) / s;
        ow[sc_idx[tid]] = (tid < 20) ? w : -w;
    }
}

extern "C" void kernel_launch(void* const* d_in, const int* in_sizes, int n_in,
                              void* d_out, int out_size) {
    const float* in = (const float*)d_in[0];
    float* out = (float*)d_out;
    int total = in_sizes[0];
    int B = total / N_COLS;
    int write_indices = (out_size >= 2 * total) ? 1 : 0;

    cudaFuncSetAttribute(pg_sort_kernel,
                         cudaFuncAttributeMaxDynamicSharedMemorySize, SMEM_BYTES);

    pg_build_table_kernel<<<64, 1024>>>();
    pg_fix_table_kernel<<<1, NT>>>();

    // Split the row range into 4 launches (profiling visibility; negligible cost).
    int chunk = (B + 3) / 4;
    for (int r0 = 0; r0 < B; r0 += chunk) {
        int nrows = (B - r0 < chunk) ? (B - r0) : chunk;
        pg_sort_kernel<<<nrows, NT, SMEM_BYTES>>>(in, out, B, write_indices, r0);
    }
}